// round 17
// baseline (speedup 1.0000x reference)
#include <cuda_runtime.h>

// Problem constants
#define TT    4096
#define FF    9
#define NSEQ  2048
#define L1    2049
#define L2    1025
#define L3    513

// Tiling: 8 tiles x 61 + 1 tail tile x 25 = 513 exactly.
#define V3A     61
#define NTILES  9
#define IN_LEN  502             // 8*61+14
#define NLOAD   (IN_LEN*FF)     // 4518
#define NPF     18              // ceil(4518/256)
#define IN_STR  516             // even -> double-aligned rows
#define S1_STR  260             // mult of 4; float4 rows; order-8 banks
#define S2_STR  132             // mult of 4; order-8 banks
#define W3_STR  97

// dup-weight pair arrays (double-typed in smem)
// w1d: [cog(8)][55 doubles]  slot = ci*6 + k*2 + ch   (55 odd -> conflict-free)
// w2d: [cog(16)][97 doubles] slot = ci*6 + k*2 + ch   (97 odd -> conflict-free)
#define OFF_S1   (9*IN_STR)                 // 4644
#define OFF_S2   (OFF_S1 + 16*S1_STR)       // 8804
#define OFF_W1D  (OFF_S2 + 32*S2_STR)       // 13028 (even -> 8B aligned)
#define OFF_W2D  (OFF_W1D + 8*55*2)         // 13908
#define OFF_W3   (OFF_W2D + 16*97*2)        // 17012
#define OFF_SB   (OFF_W3 + 16*W3_STR)       // 18564
#define OFF_FACC (OFF_SB + 64)              // 18628
#define SM_FLOATS (OFF_FACC + 256)          // 18884
#define SMEM_BYTES (SM_FLOATS * 4)          // 75536 B = 73.8KB -> 3 CTAs/SM

__device__ float g_feat[NSEQ * 16];

// ---- f32x2 pair helpers (double = aligned register pair, lanes: lo,hi) ----
__device__ __forceinline__ double ffma2(double a, double b, double c) {
    double d;
    asm("fma.rn.f32x2 %0, %1, %2, %3;" : "=d"(d) : "d"(a), "d"(b), "d"(c));
    return d;
}
__device__ __forceinline__ double mkmid(double p0, double p1) {
    // lanes (hi(p0), lo(p1)) = (x[2j+1], x[2j+2])
    return __hiloint2double(__double2loint(p1), __double2hiint(p0));
}
__device__ __forceinline__ float plo(double d) { return __int_as_float(__double2loint(d)); }
__device__ __forceinline__ float phi(double d) { return __int_as_float(__double2hiint(d)); }

__global__ __launch_bounds__(256) void cnn_main(
    const float* __restrict__ x,
    const float* __restrict__ w1, const float* __restrict__ b1,
    const float* __restrict__ w2, const float* __restrict__ b2,
    const float* __restrict__ w3, const float* __restrict__ b3)
{
    extern __shared__ float sm[];
    float*  h0   = sm;                  // [9][IN_STR]
    float*  s1   = sm + OFF_S1;         // [16][S1_STR]
    float*  s2   = sm + OFF_S2;         // [32][S2_STR]
    double* w1d  = (double*)(sm + OFF_W1D);
    double* w2d  = (double*)(sm + OFF_W2D);
    float*  sw3  = sm + OFF_W3;
    float*  sb   = sm + OFF_SB;
    float*  facc = sm + OFF_FACC;

    const int tid = threadIdx.x;
    const int n   = blockIdx.x;
    const float* xin = x + (size_t)n * (TT * FF);

    const int tl0 = tid / 9;
    const int ci0 = tid - 9 * tl0;

    // Zero all smem once: persistent zero padding.
    for (int i = tid; i < SM_FLOATS; i += 256) sm[i] = 0.f;
    __syncthreads();

    // dup weight pairs (w,w) for stages 1,2; scalar for stage 3
    for (int i = tid; i < 16*27; i += 256) {
        int co = i / 27, r = i - co*27, ci = r / 3, k = r - ci*3;
        int slot = (co >> 1)*55 + ci*6 + k*2 + (co & 1);
        float v = w1[i];
        sm[OFF_W1D + 2*slot]     = v;
        sm[OFF_W1D + 2*slot + 1] = v;
    }
    for (int i = tid; i < 32*48; i += 256) {
        int co = i / 48, r = i - co*48, ci = r / 3, k = r - ci*3;
        int slot = (co >> 1)*97 + ci*6 + k*2 + (co & 1);
        float v = w2[i];
        sm[OFF_W2D + 2*slot]     = v;
        sm[OFF_W2D + 2*slot + 1] = v;
    }
    for (int i = tid; i < 16*96; i += 256) sw3[(i/96)*W3_STR + (i%96)] = w3[i];
    if (tid < 16)      sb[tid] = b1[tid];
    else if (tid < 48) sb[tid] = b2[tid-16];
    else if (tid < 64) sb[tid] = b3[tid-48];
    __syncthreads();

    // ---- initial prefetch of tile 0 into registers ----
    float pf[NPF];
    {
        const int tb = -14;
        int tl = tl0, ci = ci0;
        #pragma unroll
        for (int it = 0; it < NPF; ++it) {
            int idx = tid + (it << 8);
            int t   = tb + tl;
            float v = 0.f;
            if (idx < NLOAD && (unsigned)t < (unsigned)TT) v = xin[t*FF + ci];
            pf[it] = v;
            ci += 4; tl += 28; if (ci >= 9) { ci -= 9; ++tl; }
        }
    }

    for (int tile = 0; tile < NTILES; ++tile) {
        const bool full = (tile < 8);
        const int V3t   = full ? V3A : 25;
        const int NBt   = full ? 512 : 248;
        const int NCt   = full ? 512 : 240;
        const int NDt   = full ? 256 : 112;
        const int va    = tile * V3A;
        const int u1b   = 4*va - 6;
        const int u2b   = 2*va - 2;

        // ---- Phase A: store prefetched regs -> h0 ----
        {
            int tl = tl0, ci = ci0;
            #pragma unroll
            for (int it = 0; it < NPF; ++it) {
                int idx = tid + (it << 8);
                if (idx < NLOAD) h0[ci*IN_STR + tl] = pf[it];
                ci += 4; tl += 28; if (ci >= 9) { ci -= 9; ++tl; }
            }
        }
        __syncthreads();

        // ---- issue next tile's LDGs; hidden by B/C/D ----
        if (tile + 1 < NTILES) {
            const int tb = 8*((tile+1)*V3A) - 14;
            int tl = tl0, ci = ci0;
            #pragma unroll
            for (int it = 0; it < NPF; ++it) {
                int idx = tid + (it << 8);
                int t   = tb + tl;
                float v = 0.f;
                if (idx < NLOAD && (unsigned)t < (unsigned)TT) v = xin[t*FF + ci];
                pf[it] = v;
                ci += 4; tl += 28; if (ci >= 9) { ci -= 9; ++tl; }
            }
        }

        // ---- Phase B: stage1 conv(9->16,k3,p2) + relu + pool2 (FFMA2) ----
        #pragma unroll
        for (int it = 0; it < 2; ++it) {
            int item = tid + it*256;
            if (item < NBt) {
                int cog = item & 7;
                int ug  = item >> 3;
                int co0 = cog * 2;
                int ul0 = ug * 4;
                double A0[4] = {0.0, 0.0, 0.0, 0.0};
                double A1[4] = {0.0, 0.0, 0.0, 0.0};
                const double* wA  = w1d + cog*55;
                const float*  hpf = h0 + 2*ul0;
                #pragma unroll
                for (int ci = 0; ci < 9; ++ci) {
                    const double* hp2 = (const double*)(hpf + ci*IN_STR);
                    double P0 = hp2[0], P1 = hp2[1], P2 = hp2[2], P3 = hp2[3], P4 = hp2[4];
                    double S0 = mkmid(P0,P1), S1 = mkmid(P1,P2), S2 = mkmid(P2,P3), S3 = mkmid(P3,P4);
                    double WA0 = wA[ci*6],   WA1 = wA[ci*6+2], WA2 = wA[ci*6+4];
                    double WB0 = wA[ci*6+1], WB1 = wA[ci*6+3], WB2 = wA[ci*6+5];
                    A0[0]=ffma2(WA0,P0,A0[0]); A0[0]=ffma2(WA1,S0,A0[0]); A0[0]=ffma2(WA2,P1,A0[0]);
                    A0[1]=ffma2(WA0,P1,A0[1]); A0[1]=ffma2(WA1,S1,A0[1]); A0[1]=ffma2(WA2,P2,A0[1]);
                    A0[2]=ffma2(WA0,P2,A0[2]); A0[2]=ffma2(WA1,S2,A0[2]); A0[2]=ffma2(WA2,P3,A0[2]);
                    A0[3]=ffma2(WA0,P3,A0[3]); A0[3]=ffma2(WA1,S3,A0[3]); A0[3]=ffma2(WA2,P4,A0[3]);
                    A1[0]=ffma2(WB0,P0,A1[0]); A1[0]=ffma2(WB1,S0,A1[0]); A1[0]=ffma2(WB2,P1,A1[0]);
                    A1[1]=ffma2(WB0,P1,A1[1]); A1[1]=ffma2(WB1,S1,A1[1]); A1[1]=ffma2(WB2,P2,A1[1]);
                    A1[2]=ffma2(WB0,P2,A1[2]); A1[2]=ffma2(WB1,S2,A1[2]); A1[2]=ffma2(WB2,P3,A1[2]);
                    A1[3]=ffma2(WB0,P3,A1[3]); A1[3]=ffma2(WB1,S3,A1[3]); A1[3]=ffma2(WB2,P4,A1[3]);
                }
                float ba = sb[co0], bb = sb[co0+1];
                float4 r0, r1;
                float* pr0 = (float*)&r0;
                float* pr1 = (float*)&r1;
                #pragma unroll
                for (int u = 0; u < 4; ++u) {
                    int ug1 = u1b + ul0 + u;
                    bool valid = (ug1 >= 0) && (ug1 < L1);
                    float v0 = fmaxf(fmaxf(plo(A0[u])+ba, 0.f), fmaxf(phi(A0[u])+ba, 0.f));
                    float v1 = fmaxf(fmaxf(plo(A1[u])+bb, 0.f), fmaxf(phi(A1[u])+bb, 0.f));
                    pr0[u] = valid ? v0 : 0.f;
                    pr1[u] = valid ? v1 : 0.f;
                }
                *(float4*)(s1 +  co0   *S1_STR + ul0) = r0;
                *(float4*)(s1 + (co0+1)*S1_STR + ul0) = r1;
            }
        }
        __syncthreads();

        // ---- Phase C: stage2 conv(16->32,k3,p2) + relu + pool2 (FFMA2) ----
        #pragma unroll
        for (int it = 0; it < 2; ++it) {
            int item = tid + it*256;
            if (item < NCt) {
                int cog = item & 15;
                int ug  = item >> 4;
                int co0 = cog * 2;
                int ul0 = ug * 4;
                double A0[4] = {0.0, 0.0, 0.0, 0.0};
                double A1[4] = {0.0, 0.0, 0.0, 0.0};
                const double* wA  = w2d + cog*97;
                const float*  hpf = s1 + 2*ul0;
                #pragma unroll 4
                for (int ci = 0; ci < 16; ++ci) {
                    const double* hp2 = (const double*)(hpf + ci*S1_STR);
                    double P0 = hp2[0], P1 = hp2[1], P2 = hp2[2], P3 = hp2[3], P4 = hp2[4];
                    double S0 = mkmid(P0,P1), S1v = mkmid(P1,P2), S2 = mkmid(P2,P3), S3 = mkmid(P3,P4);
                    double WA0 = wA[ci*6],   WA1 = wA[ci*6+2], WA2 = wA[ci*6+4];
                    double WB0 = wA[ci*6+1], WB1 = wA[ci*6+3], WB2 = wA[ci*6+5];
                    A0[0]=ffma2(WA0,P0,A0[0]); A0[0]=ffma2(WA1,S0,A0[0]);  A0[0]=ffma2(WA2,P1,A0[0]);
                    A0[1]=ffma2(WA0,P1,A0[1]); A0[1]=ffma2(WA1,S1v,A0[1]); A0[1]=ffma2(WA2,P2,A0[1]);
                    A0[2]=ffma2(WA0,P2,A0[2]); A0[2]=ffma2(WA1,S2,A0[2]);  A0[2]=ffma2(WA2,P3,A0[2]);
                    A0[3]=ffma2(WA0,P3,A0[3]); A0[3]=ffma2(WA1,S3,A0[3]);  A0[3]=ffma2(WA2,P4,A0[3]);
                    A1[0]=ffma2(WB0,P0,A1[0]); A1[0]=ffma2(WB1,S0,A1[0]);  A1[0]=ffma2(WB2,P1,A1[0]);
                    A1[1]=ffma2(WB0,P1,A1[1]); A1[1]=ffma2(WB1,S1v,A1[1]); A1[1]=ffma2(WB2,P2,A1[1]);
                    A1[2]=ffma2(WB0,P2,A1[2]); A1[2]=ffma2(WB1,S2,A1[2]);  A1[2]=ffma2(WB2,P3,A1[2]);
                    A1[3]=ffma2(WB0,P3,A1[3]); A1[3]=ffma2(WB1,S3,A1[3]);  A1[3]=ffma2(WB2,P4,A1[3]);
                }
                float ba = sb[16+co0], bb = sb[16+co0+1];
                float4 r0, r1;
                float* pr0 = (float*)&r0;
                float* pr1 = (float*)&r1;
                #pragma unroll
                for (int u = 0; u < 4; ++u) {
                    int ug2 = u2b + ul0 + u;
                    bool valid = (ug2 >= 0) && (ug2 < L2);
                    float v0 = fmaxf(fmaxf(plo(A0[u])+ba, 0.f), fmaxf(phi(A0[u])+ba, 0.f));
                    float v1 = fmaxf(fmaxf(plo(A1[u])+bb, 0.f), fmaxf(phi(A1[u])+bb, 0.f));
                    pr0[u] = valid ? v0 : 0.f;
                    pr1[u] = valid ? v1 : 0.f;
                }
                *(float4*)(s2 +  co0   *S2_STR + ul0) = r0;
                *(float4*)(s2 + (co0+1)*S2_STR + ul0) = r1;
            }
        }
        __syncthreads();

        // ---- Phase D: stage3 conv(32->16,k3,p2) + relu + pool2 + mean-acc (scalar) ----
        if (tid < NDt) {
            int co  = tid & 15;
            int ug  = tid >> 4;
            int ul0 = ug * 4;
            float acc[8];
            #pragma unroll
            for (int p = 0; p < 8; ++p) acc[p] = 0.f;
            const float* wp = sw3 + co*W3_STR;
            const float* hp = s2 + 2*ul0;
            #pragma unroll 4
            for (int ci = 0; ci < 32; ++ci) {
                float in[10];
                #pragma unroll
                for (int j = 0; j < 10; ++j) in[j] = hp[j];
                float w0=wp[0], w1_=wp[1], w2_=wp[2];
                #pragma unroll
                for (int p = 0; p < 8; ++p)
                    acc[p] += w0*in[p] + w1_*in[p+1] + w2_*in[p+2];
                wp += 3; hp += S2_STR;
            }
            float b = sb[48+co];
            float sum = 0.f;
            #pragma unroll
            for (int u = 0; u < 4; ++u) {
                int v = ul0 + u;
                if (v < V3t) {
                    float y = fmaxf(fmaxf(acc[2*u]+b, 0.f), fmaxf(acc[2*u+1]+b, 0.f));
                    sum += y;
                }
            }
            facc[tid] += sum;
        }
        __syncthreads();
    }

    // ---- mean over L3=513 positions ----
    if (tid < 16) {
        float s = 0.f;
        #pragma unroll
        for (int u = 0; u < 16; ++u) s += facc[tid + 16*u];
        g_feat[n*16 + tid] = s * (1.0f / 513.0f);
    }
}

// Final: feat [B, J*16=128] -> maxpool k=3 -> [B, 42]
__global__ void final_pool(float* __restrict__ out)
{
    int i = blockIdx.x * blockDim.x + threadIdx.x;
    if (i >= 256*42) return;
    int b = i / 42;
    int g = i - b*42;
    float m = -1e30f;
    #pragma unroll
    for (int e3 = 0; e3 < 3; ++e3) {
        int e = 3*g + e3;
        int j = e >> 4;
        int c = e & 15;
        m = fmaxf(m, g_feat[(b*8 + j)*16 + c]);
    }
    out[i] = m;
}

extern "C" void kernel_launch(void* const* d_in, const int* in_sizes, int n_in,
                              void* d_out, int out_size)
{
    (void)in_sizes; (void)n_in; (void)out_size;
    const float* x  = (const float*)d_in[0];
    const float* w1 = (const float*)d_in[1];
    const float* b1 = (const float*)d_in[2];
    const float* w2 = (const float*)d_in[3];
    const float* b2 = (const float*)d_in[4];
    const float* w3 = (const float*)d_in[5];
    const float* b3 = (const float*)d_in[6];
    float* out = (float*)d_out;

    cudaFuncSetAttribute(cnn_main, cudaFuncAttributeMaxDynamicSharedMemorySize, SMEM_BYTES);
    cnn_main<<<NSEQ, 256, SMEM_BYTES>>>(x, w1, b1, w2, b2, w3, b3);
    final_pool<<<42, 256>>>(out);
}